// round 1
// baseline (speedup 1.0000x reference)
#include <cuda_runtime.h>

// Problem constants (fixed by the dataset: B=65536, T=100, D_CP=2, D_FIN=3, HID=12, D_OUT=2)
#define BT_B 65536
#define BT_T 100
#define HID 12

// 2 * log2(e): folded into W_rnn/b_rnn so tanh(x) = 1 - 2/(exp2(a)+1) with a = 2*log2e*(xW+b)
#define TWO_LOG2E 2.8853900817779268f

__device__ __forceinline__ float ex2_approx(float x) {
    float r;
    asm("ex2.approx.f32 %0, %1;" : "=f"(r) : "f"(x));
    return r;
}

__global__ __launch_bounds__(128)
void deform_tracker_kernel(const float* __restrict__ cp,     // (B, T, 2)
                           const float* __restrict__ fin,    // (B, T, 3)
                           const float* __restrict__ Wr,     // (5, 12)
                           const float* __restrict__ br,     // (12,)
                           const float* __restrict__ Wo,     // (14, 2)
                           const float* __restrict__ bo,     // (2,)
                           float* __restrict__ out)          // (B, T, 2)
{
    // Stage weights in shared memory (broadcast reads in the loop; ptxas hoists into regs where budget allows)
    __shared__ float sWr[5][12];   // pre-scaled by 2*log2e
    __shared__ float sbr[12];      // pre-scaled by 2*log2e
    __shared__ float sWo[12][2];   // W_out rows 2..13 (the h part)
    __shared__ float sWo0[4];      // W_out rows 0..1 (the cp0 part), row-major
    __shared__ float sbo[2];

    int tid = threadIdx.x;
    if (tid < 60) sWr[tid / 12][tid % 12] = Wr[tid] * TWO_LOG2E;
    if (tid < 12) sbr[tid] = br[tid] * TWO_LOG2E;
    if (tid < 24) sWo[tid >> 1][tid & 1] = Wo[4 + tid];
    if (tid < 4)  sWo0[tid] = Wo[tid];
    if (tid < 2)  sbo[tid] = bo[tid];
    __syncthreads();

    int b = blockIdx.x * blockDim.x + tid;
    if (b >= BT_B) return;

    // cp0 = control_point_input[b, 0, :]
    const float2 cp0 = *reinterpret_cast<const float2*>(cp + (size_t)b * (BT_T * 2));

    // Loop-invariant part of the output projection: cp0 @ W_out[0:2] + b_out
    float c0 = fmaf(cp0.x, sWo0[0], fmaf(cp0.y, sWo0[2], sbo[0]));
    float c1 = fmaf(cp0.x, sWo0[1], fmaf(cp0.y, sWo0[3], sbo[1]));

    const float4* finp = reinterpret_cast<const float4*>(fin + (size_t)b * (BT_T * 3));
    float4* outp = reinterpret_cast<float4*>(out + (size_t)b * (BT_T * 2));

    float o0 = cp0.x, o1 = cp0.y;

    // 25 chunks of 4 timesteps; keep outer loop rolled so the body fits the L0 I$.
    #pragma unroll 1
    for (int c = 0; c < BT_T / 4; c++) {
        float4 fa = finp[3 * c + 0];
        float4 fb = finp[3 * c + 1];
        float4 fc = finp[3 * c + 2];
        float f[12] = {fa.x, fa.y, fa.z, fa.w,
                       fb.x, fb.y, fb.z, fb.w,
                       fc.x, fc.y, fc.z, fc.w};
        float res[8];

        #pragma unroll
        for (int s = 0; s < 4; s++) {
            const float x2 = f[3 * s + 0];
            const float x3 = f[3 * s + 1];
            const float x4 = f[3 * s + 2];

            float h[HID];
            #pragma unroll
            for (int j = 0; j < HID; j++) {
                float a = sbr[j];
                a = fmaf(o0, sWr[0][j], a);
                a = fmaf(o1, sWr[1][j], a);
                a = fmaf(x2, sWr[2][j], a);
                a = fmaf(x3, sWr[3][j], a);
                a = fmaf(x4, sWr[4][j], a);
                // tanh(x) = 1 - 2/(exp(2x)+1); a already == 2*log2e*(xW+b)
                float e = ex2_approx(a);
                h[j] = fmaf(-2.0f, __fdividef(1.0f, e + 1.0f), 1.0f);
            }

            // out = c + h @ W_out[2:14]; two partial accumulators to shorten the dep chain
            float y0a = c0, y0b = 0.0f, y1a = c1, y1b = 0.0f;
            #pragma unroll
            for (int j = 0; j < HID; j += 2) {
                y0a = fmaf(h[j],     sWo[j][0],     y0a);
                y1a = fmaf(h[j],     sWo[j][1],     y1a);
                y0b = fmaf(h[j + 1], sWo[j + 1][0], y0b);
                y1b = fmaf(h[j + 1], sWo[j + 1][1], y1b);
            }
            o0 = y0a + y0b;
            o1 = y1a + y1b;
            res[2 * s + 0] = o0;
            res[2 * s + 1] = o1;
        }

        outp[2 * c + 0] = make_float4(res[0], res[1], res[2], res[3]);
        outp[2 * c + 1] = make_float4(res[4], res[5], res[6], res[7]);
    }
}

extern "C" void kernel_launch(void* const* d_in, const int* in_sizes, int n_in,
                              void* d_out, int out_size) {
    const float* cp  = (const float*)d_in[0];  // control_point_input (B,T,2)
    const float* fin = (const float*)d_in[1];  // finger_input (B,T,3)
    const float* Wr  = (const float*)d_in[2];  // W_rnn (5,12)
    // d_in[3] = U_rnn — mathematically inert (hidden state reset each step)
    const float* br  = (const float*)d_in[4];  // b_rnn (12,)
    const float* Wo  = (const float*)d_in[5];  // W_out (14,2)
    const float* bo  = (const float*)d_in[6];  // b_out (2,)
    float* out = (float*)d_out;

    const int threads = 128;
    const int blocks = (BT_B + threads - 1) / threads;  // 512
    deform_tracker_kernel<<<blocks, threads>>>(cp, fin, Wr, br, Wo, bo, out);
}

// round 2
// speedup vs baseline: 1.2740x; 1.2740x over previous
#include <cuda_runtime.h>

// Problem constants (fixed: B=65536, T=100, D_CP=2, D_FIN=3, HID=12, D_OUT=2)
#define BT_B 65536
#define BT_T 100
#define HID 12

typedef unsigned long long u64;

__device__ __forceinline__ u64 pack2(float lo, float hi) {
    u64 r; asm("mov.b64 %0, {%1, %2};" : "=l"(r) : "f"(lo), "f"(hi)); return r;
}
__device__ __forceinline__ void unpack2(u64 v, float& lo, float& hi) {
    asm("mov.b64 {%0, %1}, %2;" : "=f"(lo), "=f"(hi) : "l"(v));
}
// Packed dual-FMA (FFMA2) — only reachable via PTX fma.rn.f32x2
__device__ __forceinline__ u64 fma2(u64 a, u64 b, u64 c) {
    u64 d; asm("fma.rn.f32x2 %0, %1, %2, %3;" : "=l"(d) : "l"(a), "l"(b), "l"(c)); return d;
}
// Hardware tanh (MUFU.TANH): 1 MUFU op instead of ex2+add+rcp+fma
__device__ __forceinline__ float tanhapx(float x) {
    float r; asm("tanh.approx.f32 %0, %1;" : "=f"(r) : "f"(x)); return r;
}

__global__ __launch_bounds__(128, 4)
void deform_tracker_kernel(const float* __restrict__ cp,     // (B, T, 2)
                           const float* __restrict__ fin,    // (B, T, 3)
                           const float* __restrict__ Wr,     // (5, 12)
                           const float* __restrict__ br,     // (12,)
                           const float* __restrict__ Wo,     // (14, 2)
                           const float* __restrict__ bo,     // (2,)
                           float* __restrict__ out)          // (B, T, 2)
{
    // Weights in shared, RNN kernel pre-packed as f32x2 pairs for FFMA2.
    __shared__ u64  sWr2[5][6];    // (Wr[i][2k], Wr[i][2k+1])
    __shared__ u64  sbr2[6];       // packed bias pairs
    __shared__ float sWo[12][2];   // W_out rows 2..13 (h part)
    __shared__ float sWo0[4];      // W_out rows 0..1 (cp0 part)
    __shared__ float sbo[2];

    int tid = threadIdx.x;
    if (tid < 30) {
        int i = tid / 6, k = tid % 6;
        sWr2[i][k] = pack2(Wr[i * 12 + 2 * k], Wr[i * 12 + 2 * k + 1]);
    }
    if (tid < 6)  sbr2[tid] = pack2(br[2 * tid], br[2 * tid + 1]);
    if (tid < 24) sWo[tid >> 1][tid & 1] = Wo[4 + tid];
    if (tid < 4)  sWo0[tid] = Wo[tid];
    if (tid < 2)  sbo[tid] = bo[tid];
    __syncthreads();

    int b = blockIdx.x * blockDim.x + tid;
    if (b >= BT_B) return;

    const float2 cp0 = *reinterpret_cast<const float2*>(cp + (size_t)b * (BT_T * 2));

    // Loop-invariant part of the output projection
    float c0 = fmaf(cp0.x, sWo0[0], fmaf(cp0.y, sWo0[2], sbo[0]));
    float c1 = fmaf(cp0.x, sWo0[1], fmaf(cp0.y, sWo0[3], sbo[1]));

    const float4* finp = reinterpret_cast<const float4*>(fin + (size_t)b * (BT_T * 3));
    float4* outp = reinterpret_cast<float4*>(out + (size_t)b * (BT_T * 2));

    float o0 = cp0.x, o1 = cp0.y;

    #pragma unroll 1
    for (int c = 0; c < BT_T / 4; c++) {
        float4 fa = finp[3 * c + 0];
        float4 fb = finp[3 * c + 1];
        float4 fc = finp[3 * c + 2];
        float f[12] = {fa.x, fa.y, fa.z, fa.w,
                       fb.x, fb.y, fb.z, fb.w,
                       fc.x, fc.y, fc.z, fc.w};
        float res[8];

        #pragma unroll
        for (int s = 0; s < 4; s++) {
            // Broadcast the 5 scalar inputs into packed pairs
            u64 px[5];
            px[0] = pack2(o0, o0);
            px[1] = pack2(o1, o1);
            px[2] = pack2(f[3 * s + 0], f[3 * s + 0]);
            px[3] = pack2(f[3 * s + 1], f[3 * s + 1]);
            px[4] = pack2(f[3 * s + 2], f[3 * s + 2]);

            // a = x @ W_rnn + b_rnn as 6 packed lanes (30 FFMA2 instead of 60 FFMA)
            u64 acc[6];
            #pragma unroll
            for (int k = 0; k < 6; k++) acc[k] = sbr2[k];
            #pragma unroll
            for (int i = 0; i < 5; i++) {
                #pragma unroll
                for (int k = 0; k < 6; k++) acc[k] = fma2(px[i], sWr2[i][k], acc[k]);
            }

            // h = tanh(a) — hardware MUFU.TANH
            float h[HID];
            #pragma unroll
            for (int k = 0; k < 6; k++) {
                float a0, a1;
                unpack2(acc[k], a0, a1);
                h[2 * k + 0] = tanhapx(a0);
                h[2 * k + 1] = tanhapx(a1);
            }

            // out = c + h @ W_out[2:14]; split accumulators to shorten dep chain
            float y0a = c0, y0b = 0.0f, y1a = c1, y1b = 0.0f;
            #pragma unroll
            for (int j = 0; j < HID; j += 2) {
                y0a = fmaf(h[j],     sWo[j][0],     y0a);
                y1a = fmaf(h[j],     sWo[j][1],     y1a);
                y0b = fmaf(h[j + 1], sWo[j + 1][0], y0b);
                y1b = fmaf(h[j + 1], sWo[j + 1][1], y1b);
            }
            o0 = y0a + y0b;
            o1 = y1a + y1b;
            res[2 * s + 0] = o0;
            res[2 * s + 1] = o1;
        }

        outp[2 * c + 0] = make_float4(res[0], res[1], res[2], res[3]);
        outp[2 * c + 1] = make_float4(res[4], res[5], res[6], res[7]);
    }
}

extern "C" void kernel_launch(void* const* d_in, const int* in_sizes, int n_in,
                              void* d_out, int out_size) {
    const float* cp  = (const float*)d_in[0];  // control_point_input (B,T,2)
    const float* fin = (const float*)d_in[1];  // finger_input (B,T,3)
    const float* Wr  = (const float*)d_in[2];  // W_rnn (5,12)
    // d_in[3] = U_rnn — mathematically inert (hidden state reset each step)
    const float* br  = (const float*)d_in[4];  // b_rnn (12,)
    const float* Wo  = (const float*)d_in[5];  // W_out (14,2)
    const float* bo  = (const float*)d_in[6];  // b_out (2,)
    float* out = (float*)d_out;

    const int threads = 128;
    const int blocks = (BT_B + threads - 1) / threads;  // 512, single wave at 4 CTAs/SM
    deform_tracker_kernel<<<blocks, threads>>>(cp, fin, Wr, br, Wo, bo, out);
}